// round 14
// baseline (speedup 1.0000x reference)
#include <cuda_runtime.h>
#include <cuda_fp16.h>
#include <math.h>
#include <stdint.h>

// Problem constants
constexpr int Bz = 8;
constexpr int Nq = 256;
constexpr int Mc = 1024;
constexpr int Cd = 1024;
constexpr int Hh = 16;

// Scratch
__device__ __half g_hQ[Bz * Nq * Cd];
__device__ __half g_hK[Bz * Mc * Cd];
__device__ __half g_hV[Bz * Mc * Cd];
__device__ __half g_hO[Bz * Nq * Cd];
__device__ __half g_hq[Bz * Nq * Cd];
__device__ __half g_hc[Bz * Mc * Cd];
__device__ __half g_w0[Cd * Cd];
__device__ __half g_w1[Cd * Cd];
__device__ __half g_w2[Cd * Cd];
__device__ __half g_w3[Cd * Cd];

// ---------------------------------------------------------------------------
// PTX helpers
// ---------------------------------------------------------------------------
__device__ __forceinline__ void cp_async16(uint32_t saddr, const void* gptr) {
    asm volatile("cp.async.ca.shared.global [%0], [%1], 16;" ::
                 "r"(saddr), "l"(gptr));
}
__device__ __forceinline__ void cp_commit() { asm volatile("cp.async.commit_group;"); }
__device__ __forceinline__ void cp_wait0()  { asm volatile("cp.async.wait_group 0;"); }
__device__ __forceinline__ void cp_wait1()  { asm volatile("cp.async.wait_group 1;"); }

__device__ __forceinline__ void mma_f16_16816(float c[4], uint32_t a0, uint32_t a1,
                                              uint32_t a2, uint32_t a3,
                                              uint32_t b0, uint32_t b1) {
    asm volatile(
        "mma.sync.aligned.m16n8k16.row.col.f32.f16.f16.f32 "
        "{%0,%1,%2,%3}, {%4,%5,%6,%7}, {%8,%9}, {%0,%1,%2,%3};"
        : "+f"(c[0]), "+f"(c[1]), "+f"(c[2]), "+f"(c[3])
        : "r"(a0), "r"(a1), "r"(a2), "r"(a3), "r"(b0), "r"(b1));
}
__device__ __forceinline__ void ldsm_x4(uint32_t& r0, uint32_t& r1, uint32_t& r2,
                                        uint32_t& r3, uint32_t addr) {
    asm volatile("ldmatrix.sync.aligned.m8n8.x4.shared.b16 {%0,%1,%2,%3}, [%4];"
                 : "=r"(r0), "=r"(r1), "=r"(r2), "=r"(r3) : "r"(addr));
}
__device__ __forceinline__ void ldsm_x2(uint32_t& r0, uint32_t& r1, uint32_t addr) {
    asm volatile("ldmatrix.sync.aligned.m8n8.x2.shared.b16 {%0,%1}, [%2];"
                 : "=r"(r0), "=r"(r1) : "r"(addr));
}
__device__ __forceinline__ void ldsm_x2t(uint32_t& r0, uint32_t& r1, uint32_t addr) {
    asm volatile("ldmatrix.sync.aligned.m8n8.x2.trans.shared.b16 {%0,%1}, [%2];"
                 : "=r"(r0), "=r"(r1) : "r"(addr));
}
__device__ __forceinline__ uint32_t h2u(__half2 h) {
    return *reinterpret_cast<uint32_t*>(&h);
}

// ---------------------------------------------------------------------------
// Merged fp32->fp16 conversion (one launch)
// ---------------------------------------------------------------------------
constexpr int CVT_NQ = Bz * Nq * Cd / 4;
constexpr int CVT_NC = Bz * Mc * Cd / 4;
constexpr int CVT_NW = Cd * Cd / 4;
constexpr int CVT_TOTAL = CVT_NQ + CVT_NC + 4 * CVT_NW;

__global__ void cvt_all_kernel(const float* __restrict__ q, const float* __restrict__ c,
                               const float* __restrict__ wq, const float* __restrict__ wk,
                               const float* __restrict__ wv, const float* __restrict__ wp,
                               __half* hq, __half* hc, __half* h0, __half* h1,
                               __half* h2, __half* h3) {
    int i = blockIdx.x * blockDim.x + threadIdx.x;
    if (i >= CVT_TOTAL) return;
    const float* in; __half* out; int off;
    if (i < CVT_NQ)                    { in = q;  out = hq; off = i; }
    else if (i < CVT_NQ + CVT_NC)      { in = c;  out = hc; off = i - CVT_NQ; }
    else {
        int j = i - CVT_NQ - CVT_NC;
        int seg = j / CVT_NW;
        off = j - seg * CVT_NW;
        in  = (seg == 0) ? wq : (seg == 1) ? wk : (seg == 2) ? wv : wp;
        out = (seg == 0) ? h0 : (seg == 1) ? h1 : (seg == 2) ? h2 : h3;
    }
    float4 v = ((const float4*)in)[off];
    ((__half2*)out)[2 * off]     = __floats2half2_rn(v.x, v.y);
    ((__half2*)out)[2 * off + 1] = __floats2half2_rn(v.z, v.w);
}

// ---------------------------------------------------------------------------
// Shared GEMM body (R10-proven): 128x128 CTA, 8 warps (2m x 4n), kTile=64.
// fp16 output, optional fused LayerNorm (64-col groups).
// ---------------------------------------------------------------------------
constexpr int GEMM_SMEM = 2 * 2 * 128 * 72 * 2;  // 73728

__device__ __forceinline__
void gemm_body_f16(const __half* __restrict__ A, const __half* __restrict__ Bw,
                   __half* __restrict__ Ch, const float* __restrict__ gamma,
                   const float* __restrict__ beta, int brow, int bcol,
                   int Nb, int K, __half* smh) {
    __half* As = smh;
    __half* Bs = smh + 2 * 128 * 72;

    const int tid  = threadIdx.x;
    const int lane = tid & 31;
    const int w    = tid >> 5;
    const int wm   = (w & 1) * 64;
    const int wn   = (w >> 1) * 32;
    const int g    = lane >> 2;
    const int ti   = lane & 3;
    const int lt   = lane >> 3;
    const int lr8  = lane & 7;

    const int lrow = tid >> 1;
    const int lh   = (tid & 1) * 32;
    const __half* Ag = A  + (size_t)(brow + lrow) * K + lh;
    const __half* Bg = Bw + (size_t)(bcol + lrow) * K + lh;
    const uint32_t sa = (uint32_t)__cvta_generic_to_shared(&As[lrow * 72 + lh]);
    const uint32_t sb = (uint32_t)__cvta_generic_to_shared(&Bs[lrow * 72 + lh]);
    const uint32_t asBase = (uint32_t)__cvta_generic_to_shared(As);
    const uint32_t bsBase = (uint32_t)__cvta_generic_to_shared(Bs);
    const uint32_t stageB = 128 * 72 * 2;

    uint32_t aoff[4], boff[2];
#pragma unroll
    for (int mt = 0; mt < 4; mt++) {
        int row = wm + mt * 16 + ((lt & 1) << 3) + lr8;
        int col = (lt >> 1) << 3;
        aoff[mt] = (uint32_t)((row * 72 + col) * 2);
    }
#pragma unroll
    for (int p = 0; p < 2; p++) {
        int row = wn + p * 16 + ((lt >> 1) << 3) + lr8;
        int col = (lt & 1) << 3;
        boff[p] = (uint32_t)((row * 72 + col) * 2);
    }

    float c[4][4][4];
#pragma unroll
    for (int mt = 0; mt < 4; mt++)
#pragma unroll
        for (int nt = 0; nt < 4; nt++)
#pragma unroll
            for (int e = 0; e < 4; e++) c[mt][nt][e] = 0.f;

    const int niter = K / 64;

#pragma unroll
    for (int v = 0; v < 4; v++) {
        cp_async16(sa + v * 16, Ag + v * 8);
        cp_async16(sb + v * 16, Bg + v * 8);
    }
    cp_commit();
    cp_wait0();
    __syncthreads();

    for (int t = 0; t < niter; t++) {
        if (t + 1 < niter) {
            const int k0 = (t + 1) * 64;
            const uint32_t so = ((t + 1) & 1) * stageB;
#pragma unroll
            for (int v = 0; v < 4; v++) {
                cp_async16(sa + so + v * 16, Ag + k0 + v * 8);
                cp_async16(sb + so + v * 16, Bg + k0 + v * 8);
            }
            cp_commit();
        }

        const uint32_t so = (t & 1) * stageB;

#pragma unroll
        for (int ks = 0; ks < 4; ks++) {
            const uint32_t kk2 = ks * 32;
            uint32_t a[4][4], b[4][2];
#pragma unroll
            for (int mt = 0; mt < 4; mt++)
                ldsm_x4(a[mt][0], a[mt][1], a[mt][2], a[mt][3],
                        asBase + so + aoff[mt] + kk2);
#pragma unroll
            for (int p = 0; p < 2; p++)
                ldsm_x4(b[2 * p][0], b[2 * p][1], b[2 * p + 1][0], b[2 * p + 1][1],
                        bsBase + so + boff[p] + kk2);
#pragma unroll
            for (int mt = 0; mt < 4; mt++)
#pragma unroll
                for (int nt = 0; nt < 4; nt++)
                    mma_f16_16816(c[mt][nt], a[mt][0], a[mt][1], a[mt][2],
                                  a[mt][3], b[nt][0], b[nt][1]);
        }

        if (t + 1 < niter) {
            cp_wait0();
            __syncthreads();
        }
    }

    if (gamma != nullptr) {
        __syncthreads();
        float* St = (float*)smh;   // [128][132]
#pragma unroll
        for (int mt = 0; mt < 4; mt++)
#pragma unroll
            for (int nt = 0; nt < 4; nt++) {
                const int r0 = wm + mt * 16 + g;
                const int c0 = wn + nt * 8 + 2 * ti;
                *(float2*)&St[r0 * 132 + c0] =
                    make_float2(c[mt][nt][0], c[mt][nt][1]);
                *(float2*)&St[(r0 + 8) * 132 + c0] =
                    make_float2(c[mt][nt][2], c[mt][nt][3]);
            }
        __syncthreads();

        const int row = tid & 127;
        const int grp = tid >> 7;
        const float* pr = St + row * 132 + grp * 64;
        float s = 0.f, sq = 0.f;
#pragma unroll
        for (int i2 = 0; i2 < 16; i2++) {
            float4 v = *(const float4*)(pr + i2 * 4);
            s  += v.x + v.y + v.z + v.w;
            sq += v.x * v.x + v.y * v.y + v.z * v.z + v.w * v.w;
        }
        const float mean = s * (1.f / 64.f);
        const float var  = sq * (1.f / 64.f) - mean * mean;
        const float rstd = rsqrtf(var + 1e-5f);

        __half* yp = Ch + (size_t)(brow + row) * Nb + bcol + grp * 64;
#pragma unroll
        for (int i2 = 0; i2 < 16; i2++) {
            float4 v  = *(const float4*)(pr + i2 * 4);
            float4 gv = *(const float4*)(gamma + i2 * 4);
            float4 bv = *(const float4*)(beta + i2 * 4);
            *(__half2*)(yp + i2 * 4) =
                __floats2half2_rn((v.x - mean) * rstd * gv.x + bv.x,
                                  (v.y - mean) * rstd * gv.y + bv.y);
            *(__half2*)(yp + i2 * 4 + 2) =
                __floats2half2_rn((v.z - mean) * rstd * gv.z + bv.z,
                                  (v.w - mean) * rstd * gv.w + bv.w);
        }
        return;
    }

#pragma unroll
    for (int mt = 0; mt < 4; mt++) {
#pragma unroll
        for (int nt = 0; nt < 4; nt++) {
            const int row0 = brow + wm + mt * 16 + g;
            const int col0 = bcol + wn + nt * 8 + 2 * ti;
            *(__half2*)(Ch + (size_t)row0 * Nb + col0) =
                __floats2half2_rn(c[mt][nt][0], c[mt][nt][1]);
            *(__half2*)(Ch + (size_t)(row0 + 8) * Nb + col0) =
                __floats2half2_rn(c[mt][nt][2], c[mt][nt][3]);
        }
    }
}

// Merged Q/K/V projection launch: 1152 CTAs, flattened dispatch.
__global__ __launch_bounds__(256, 2)
void qkv_kernel(const __half* __restrict__ hq, const __half* __restrict__ hc,
                const __half* __restrict__ w0, const __half* __restrict__ w1,
                const __half* __restrict__ w2,
                __half* __restrict__ hQ, __half* __restrict__ hK,
                __half* __restrict__ hV,
                const float* __restrict__ qg, const float* __restrict__ qb,
                const float* __restrict__ kg, const float* __restrict__ kb) {
    extern __shared__ __half smh[];
    const int bxx = blockIdx.x;
    const __half *A, *Bw;
    __half* Ch;
    const float *gamma, *beta;
    int gx, gy;
    if (bxx < 128) {
        gx = bxx & 7; gy = bxx >> 3;
        A = hq; Bw = w0; Ch = hQ; gamma = qg; beta = qb;
    } else if (bxx < 640) {
        int idx = bxx - 128;
        gx = idx & 7; gy = idx >> 3;
        A = hc; Bw = w1; Ch = hK; gamma = kg; beta = kb;
    } else {
        int idx = bxx - 640;
        gx = idx & 7; gy = idx >> 3;
        A = hc; Bw = w2; Ch = hV; gamma = nullptr; beta = nullptr;
    }
    gemm_body_f16(A, Bw, Ch, gamma, beta, gy * 128, gx * 128, Cd, Cd, smh);
}

// ---------------------------------------------------------------------------
// Output projection: 128x64 CTA tile (8 warps, 64x16 warp tile), fp32 + bias.
// grid (Nb/64, Ma/128) = (16,16) = 256 CTAs.
// ---------------------------------------------------------------------------
constexpr int GEMM_OUT_SMEM = 2 * (128 + 64) * 72 * 2;  // 55296

__global__ __launch_bounds__(256, 2)
void gemm_out_kernel(const __half* __restrict__ A, const __half* __restrict__ Bw,
                     const float* __restrict__ bias, float* __restrict__ Cc,
                     int Nb, int K) {
    extern __shared__ __half smh[];
    __half* As = smh;                    // [2][128][72]
    __half* Bs = smh + 2 * 128 * 72;     // [2][64][72]

    const int tid  = threadIdx.x;
    const int lane = tid & 31;
    const int w    = tid >> 5;
    const int wm   = (w & 1) * 64;
    const int wn   = (w >> 1) * 16;
    const int g    = lane >> 2;
    const int ti   = lane & 3;
    const int lt   = lane >> 3;
    const int lr8  = lane & 7;
    const int brow = blockIdx.y * 128;
    const int bcol = blockIdx.x * 64;

    // A: 128 rows (2 threads/row, 64B each); B: 64 rows (4 threads/row, 32B each)
    const int lrow = tid >> 1;
    const int lh   = (tid & 1) * 32;
    const __half* Ag = A + (size_t)(brow + lrow) * K + lh;
    const int brw = tid >> 2;
    const int bho = (tid & 3) * 16;
    const __half* Bg = Bw + (size_t)(bcol + brw) * K + bho;
    const uint32_t sa = (uint32_t)__cvta_generic_to_shared(&As[lrow * 72 + lh]);
    const uint32_t sb = (uint32_t)__cvta_generic_to_shared(&Bs[brw * 72 + bho]);
    const uint32_t asBase = (uint32_t)__cvta_generic_to_shared(As);
    const uint32_t bsBase = (uint32_t)__cvta_generic_to_shared(Bs);
    const uint32_t stageA = 128 * 72 * 2;
    const uint32_t stageBB = 64 * 72 * 2;

    uint32_t aoff[4], boff;
#pragma unroll
    for (int mt = 0; mt < 4; mt++) {
        int row = wm + mt * 16 + ((lt & 1) << 3) + lr8;
        int col = (lt >> 1) << 3;
        aoff[mt] = (uint32_t)((row * 72 + col) * 2);
    }
    {
        int row = wn + ((lt >> 1) << 3) + lr8;
        int col = (lt & 1) << 3;
        boff = (uint32_t)((row * 72 + col) * 2);
    }

    float c[4][2][4];
#pragma unroll
    for (int mt = 0; mt < 4; mt++)
#pragma unroll
        for (int nt = 0; nt < 2; nt++)
#pragma unroll
            for (int e = 0; e < 4; e++) c[mt][nt][e] = 0.f;

    const int niter = K / 64;

#pragma unroll
    for (int v = 0; v < 4; v++) cp_async16(sa + v * 16, Ag + v * 8);
#pragma unroll
    for (int v = 0; v < 2; v++) cp_async16(sb + v * 16, Bg + v * 8);
    cp_commit();
    cp_wait0();
    __syncthreads();

    for (int t = 0; t < niter; t++) {
        if (t + 1 < niter) {
            const int k0 = (t + 1) * 64;
            const uint32_t soA = ((t + 1) & 1) * stageA;
            const uint32_t soB = ((t + 1) & 1) * stageBB;
#pragma unroll
            for (int v = 0; v < 4; v++) cp_async16(sa + soA + v * 16, Ag + k0 + v * 8);
#pragma unroll
            for (int v = 0; v < 2; v++) cp_async16(sb + soB + v * 16, Bg + k0 + v * 8);
            cp_commit();
        }

        const uint32_t soA = (t & 1) * stageA;
        const uint32_t soB = (t & 1) * stageBB;

#pragma unroll
        for (int ks = 0; ks < 4; ks++) {
            const uint32_t kk2 = ks * 32;
            uint32_t a[4][4], b[2][2];
#pragma unroll
            for (int mt = 0; mt < 4; mt++)
                ldsm_x4(a[mt][0], a[mt][1], a[mt][2], a[mt][3],
                        asBase + soA + aoff[mt] + kk2);
            ldsm_x4(b[0][0], b[0][1], b[1][0], b[1][1], bsBase + soB + boff + kk2);
#pragma unroll
            for (int mt = 0; mt < 4; mt++)
#pragma unroll
                for (int nt = 0; nt < 2; nt++)
                    mma_f16_16816(c[mt][nt], a[mt][0], a[mt][1], a[mt][2],
                                  a[mt][3], b[nt][0], b[nt][1]);
        }

        if (t + 1 < niter) {
            cp_wait0();
            __syncthreads();
        }
    }

#pragma unroll
    for (int mt = 0; mt < 4; mt++) {
#pragma unroll
        for (int nt = 0; nt < 2; nt++) {
            const int row0 = brow + wm + mt * 16 + g;
            const int col0 = bcol + wn + nt * 8 + 2 * ti;
            const float b0 = bias[col0], b1 = bias[col0 + 1];
            *(float2*)(Cc + (size_t)row0 * Nb + col0) =
                make_float2(c[mt][nt][0] + b0, c[mt][nt][1] + b1);
            *(float2*)(Cc + (size_t)(row0 + 8) * Nb + col0) =
                make_float2(c[mt][nt][2] + b0, c[mt][nt][3] + b1);
        }
    }
}

// ---------------------------------------------------------------------------
// Fused attention, 3-buffer pipeline. AV pass: warps split by chunk parity
// (warps 0-3 even chunks, 4-7 odd), 16-wide d-slabs, smem reduction at end.
// ---------------------------------------------------------------------------
constexpr int SPITCH   = 1028;
constexpr int ATT_SMEM = 32 * SPITCH * 4 + 32 * 72 * 2 + 3 * 64 * 72 * 2;  // 163840

__global__ __launch_bounds__(256)
void attention_kernel(const __half* __restrict__ Qh16, const __half* __restrict__ Kh16,
                      const __half* __restrict__ Vh16, const int* __restrict__ mask,
                      float* __restrict__ attn, __half* __restrict__ O) {
    extern __shared__ char smraw[];
    float*  S  = (float*)smraw;
    __half* Qh = (__half*)(smraw + 32 * SPITCH * 4);
    __half* KV = (__half*)(smraw + 32 * SPITCH * 4 + 32 * 72 * 2);  // [3][64][72]

    const int bh = blockIdx.y;
    const int b  = bh >> 4;
    const int h  = bh & 15;
    const int n0 = blockIdx.x * 32;
    const int tid  = threadIdx.x;
    const int lane = tid & 31;
    const int w    = tid >> 5;
    const int g    = lane >> 2;
    const int ti   = lane & 3;
    const int lt   = lane >> 3;
    const int lr8  = lane & 7;
    const int l16  = lane & 15;

    const uint32_t sBase  = (uint32_t)__cvta_generic_to_shared(smraw);
    const uint32_t qBase  = (uint32_t)__cvta_generic_to_shared(Qh);
    const uint32_t kvBase = (uint32_t)__cvta_generic_to_shared(KV);
    const uint32_t bufB   = 64 * 72 * 2;  // 9216

    {
        const int n  = tid >> 3;
        const int d0 = (tid & 7) * 8;
        const __half* qp = Qh16 + (size_t)(b * Nq + n0 + n) * Cd + h * 64 + d0;
        *(uint4*)&Qh[n * 72 + d0] = *(const uint4*)qp;
    }
    __syncthreads();

    uint32_t qa[4][2][4];
#pragma unroll
    for (int mt = 0; mt < 2; mt++) {
        const uint32_t off = qBase +
            (uint32_t)(((mt * 16 + ((lt & 1) << 3) + lr8) * 72 + ((lt >> 1) << 3)) * 2);
#pragma unroll
        for (int ks = 0; ks < 4; ks++)
            ldsm_x4(qa[ks][mt][0], qa[ks][mt][1], qa[ks][mt][2], qa[ks][mt][3],
                    off + ks * 32);
    }

    const int stM  = tid >> 2;
    const int stD0 = (tid & 3) * 16;
    const uint32_t stOff = (uint32_t)((stM * 72 + stD0) * 2);
    const __half* Kbase = Kh16 + (size_t)(b * Mc + stM) * Cd + h * 64 + stD0;
    const __half* Vbase = Vh16 + (size_t)(b * Mc + stM) * Cd + h * 64 + stD0;

    const float scale = 0.125f;
    const uint32_t kboff = (uint32_t)(((w * 8 + (l16 & 7)) * 72 + ((l16 >> 3) << 3)) * 2);

    // ---- pass 1: scores ----
#pragma unroll
    for (int p = 0; p < 2; p++) {
        const uint32_t dst = kvBase + p * bufB + stOff;
        const __half* kp = Kbase + (size_t)p * 64 * Cd;
        cp_async16(dst, kp);
        cp_async16(dst + 16, kp + 8);
        cp_commit();
    }

    for (int j = 0; j < 16; j++) {
        if (j < 15) cp_wait1(); else cp_wait0();
        __syncthreads();
        if (j + 2 < 16) {
            const uint32_t dst = kvBase + ((j + 2) % 3) * bufB + stOff;
            const __half* kp = Kbase + (size_t)(j + 2) * 64 * Cd;
            cp_async16(dst, kp);
            cp_async16(dst + 16, kp + 8);
            cp_commit();
        }

        float c[2][4];
#pragma unroll
        for (int mt = 0; mt < 2; mt++)
#pragma unroll
            for (int e = 0; e < 4; e++) c[mt][e] = 0.f;

        const uint32_t kb = kvBase + (j % 3) * bufB + kboff;
#pragma unroll
        for (int ks = 0; ks < 4; ks++) {
            uint32_t b0, b1;
            ldsm_x2(b0, b1, kb + ks * 32);
            mma_f16_16816(c[0], qa[ks][0][0], qa[ks][0][1], qa[ks][0][2],
                          qa[ks][0][3], b0, b1);
            mma_f16_16816(c[1], qa[ks][1][0], qa[ks][1][1], qa[ks][1][2],
                          qa[ks][1][3], b0, b1);
        }

        const int m0 = j * 64 + w * 8 + 2 * ti;
        const bool ok0 = mask[b * Mc + m0] != 0;
        const bool ok1 = mask[b * Mc + m0 + 1] != 0;
#pragma unroll
        for (int mt = 0; mt < 2; mt++) {
            const int r = mt * 16 + g;
            S[r * SPITCH + m0]           = ok0 ? c[mt][0] * scale : -1e30f;
            S[r * SPITCH + m0 + 1]       = ok1 ? c[mt][1] * scale : -1e30f;
            S[(r + 8) * SPITCH + m0]     = ok0 ? c[mt][2] * scale : -1e30f;
            S[(r + 8) * SPITCH + m0 + 1] = ok1 ? c[mt][3] * scale : -1e30f;
        }
    }
    __syncthreads();

    // prefetch V chunks 0,1 — overlaps with softmax
#pragma unroll
    for (int p = 0; p < 2; p++) {
        const uint32_t dst = kvBase + p * bufB + stOff;
        const __half* vp = Vbase + (size_t)p * 64 * Cd;
        cp_async16(dst, vp);
        cp_async16(dst + 16, vp + 8);
        cp_commit();
    }

    // ---- pass 2: softmax; write attn fp32 + fp16 in-place ----
    for (int r = 0; r < 4; r++) {
        const int n = w * 4 + r;
        float* p = S + (size_t)n * SPITCH;

        float4 v[8];
        float mx = -1e30f;
#pragma unroll
        for (int i = 0; i < 8; i++) {
            v[i] = *(const float4*)(p + (i * 32 + lane) * 4);
            mx = fmaxf(mx, fmaxf(fmaxf(v[i].x, v[i].y), fmaxf(v[i].z, v[i].w)));
        }
#pragma unroll
        for (int o = 16; o > 0; o >>= 1) mx = fmaxf(mx, __shfl_xor_sync(0xFFFFFFFFu, mx, o));

        float sum = 0.f;
#pragma unroll
        for (int i = 0; i < 8; i++) {
            v[i].x = __expf(v[i].x - mx);
            v[i].y = __expf(v[i].y - mx);
            v[i].z = __expf(v[i].z - mx);
            v[i].w = __expf(v[i].w - mx);
            sum += v[i].x + v[i].y + v[i].z + v[i].w;
        }
#pragma unroll
        for (int o = 16; o > 0; o >>= 1) sum += __shfl_xor_sync(0xFFFFFFFFu, sum, o);
        const float inv = 1.f / sum;

        float*  op = attn + ((size_t)bh * Nq + n0 + n) * Mc;
        __half* ph = (__half*)p;
#pragma unroll
        for (int i = 0; i < 8; i++) {
            const int m0 = (i * 32 + lane) * 4;
            v[i].x *= inv; v[i].y *= inv; v[i].z *= inv; v[i].w *= inv;
            *(float4*)(op + m0) = v[i];
            uint2 hp;
            hp.x = h2u(__floats2half2_rn(v[i].x, v[i].y));
            hp.y = h2u(__floats2half2_rn(v[i].z, v[i].w));
            *(uint2*)(ph + m0) = hp;
        }
    }

    // ---- pass 3: AV, chunk-parity warp split ----
    uint32_t sfoff[2];
#pragma unroll
    for (int mt = 0; mt < 2; mt++) {
        const int row = mt * 16 + ((lt & 1) << 3) + lr8;
        sfoff[mt] = (uint32_t)(row * (SPITCH * 4) + (((lt >> 1) << 3)) * 2);
    }
    const int dw   = w & 3;          // d-slab [dw*16, dw*16+16)
    const int wpar = w >> 2;         // chunk parity this warp handles
    const uint32_t vboff0 = (uint32_t)((l16 * 72 + dw * 16) * 2);
    const uint32_t vboff1 = vboff0 + 16;  // +8 cols

    float o2[2][2][4];
#pragma unroll
    for (int mt = 0; mt < 2; mt++)
#pragma unroll
        for (int nt = 0; nt < 2; nt++)
#pragma unroll
            for (int e = 0; e < 4; e++) o2[mt][nt][e] = 0.f;

    for (int j = 0; j < 16; j++) {
        if (j < 15) cp_wait1(); else cp_wait0();
        __syncthreads();
        if (j + 2 < 16) {
            const uint32_t dst = kvBase + ((j + 2) % 3) * bufB + stOff;
            const __half* vp = Vbase + (size_t)(j + 2) * 64 * Cd;
            cp_async16(dst, vp);
            cp_async16(dst + 16, vp + 8);
            cp_commit();
        }

        if ((j & 1) == wpar) {
            const uint32_t vb = kvBase + (j % 3) * bufB;
#pragma unroll
            for (int ks = 0; ks < 4; ks++) {
                uint32_t a[2][4], b0[2], b1[2];
                const uint32_t colB = (uint32_t)((j * 64 + ks * 16) * 2);
#pragma unroll
                for (int mt = 0; mt < 2; mt++)
                    ldsm_x4(a[mt][0], a[mt][1], a[mt][2], a[mt][3],
                            sBase + sfoff[mt] + colB);
                ldsm_x2t(b0[0], b1[0], vb + vboff0 + ks * 2304);
                ldsm_x2t(b0[1], b1[1], vb + vboff1 + ks * 2304);
#pragma unroll
                for (int mt = 0; mt < 2; mt++)
#pragma unroll
                    for (int nt = 0; nt < 2; nt++)
                        mma_f16_16816(o2[mt][nt], a[mt][0], a[mt][1], a[mt][2],
                                      a[mt][3], b0[nt], b1[nt]);
            }
        }
    }

    // reduce parity pairs: warps 4-7 -> smem (KV area, free now), warps 0-3 add
    __syncthreads();
    float* red = (float*)KV;   // [4 wq][16 e][32 lane] = 8192 B
    if (wpar == 1) {
#pragma unroll
        for (int mt = 0; mt < 2; mt++)
#pragma unroll
            for (int nt = 0; nt < 2; nt++)
#pragma unroll
                for (int e = 0; e < 4; e++)
                    red[dw * 512 + (mt * 8 + nt * 4 + e) * 32 + lane] = o2[mt][nt][e];
    }
    __syncthreads();
    if (wpar == 0) {
#pragma unroll
        for (int mt = 0; mt < 2; mt++)
#pragma unroll
            for (int nt = 0; nt < 2; nt++)
#pragma unroll
                for (int e = 0; e < 4; e++)
                    o2[mt][nt][e] += red[dw * 512 + (mt * 8 + nt * 4 + e) * 32 + lane];

#pragma unroll
        for (int mt = 0; mt < 2; mt++)
#pragma unroll
            for (int nt = 0; nt < 2; nt++) {
                const int r = mt * 16 + g;
                const int col = h * 64 + dw * 16 + nt * 8 + 2 * ti;
                *(__half2*)(O + (size_t)(b * Nq + n0 + r) * Cd + col) =
                    __floats2half2_rn(o2[mt][nt][0], o2[mt][nt][1]);
                *(__half2*)(O + (size_t)(b * Nq + n0 + r + 8) * Cd + col) =
                    __floats2half2_rn(o2[mt][nt][2], o2[mt][nt][3]);
            }
    }
}

// ---------------------------------------------------------------------------
// Launch
// ---------------------------------------------------------------------------
extern "C" void kernel_launch(void* const* d_in, const int* in_sizes, int n_in,
                              void* d_out, int out_size) {
    const float* query   = (const float*)d_in[0];
    const float* context = (const float*)d_in[1];
    const int*   mask    = (const int*)d_in[2];
    const float* Wq      = (const float*)d_in[3];
    const float* Wk      = (const float*)d_in[4];
    const float* Wv      = (const float*)d_in[5];
    const float* qg      = (const float*)d_in[6];
    const float* qb      = (const float*)d_in[7];
    const float* kg      = (const float*)d_in[8];
    const float* kb      = (const float*)d_in[9];
    const float* Wp      = (const float*)d_in[10];
    const float* bp      = (const float*)d_in[11];

    float* out  = (float*)d_out;
    float* attn = out + (size_t)Bz * Nq * Cd;

    __half *hQ, *hK, *hV, *hO, *hq, *hc, *w0, *w1, *w2, *w3;
    cudaGetSymbolAddress((void**)&hQ, g_hQ);
    cudaGetSymbolAddress((void**)&hK, g_hK);
    cudaGetSymbolAddress((void**)&hV, g_hV);
    cudaGetSymbolAddress((void**)&hO, g_hO);
    cudaGetSymbolAddress((void**)&hq, g_hq);
    cudaGetSymbolAddress((void**)&hc, g_hc);
    cudaGetSymbolAddress((void**)&w0, g_w0);
    cudaGetSymbolAddress((void**)&w1, g_w1);
    cudaGetSymbolAddress((void**)&w2, g_w2);
    cudaGetSymbolAddress((void**)&w3, g_w3);

    cudaFuncSetAttribute(qkv_kernel,
                         cudaFuncAttributeMaxDynamicSharedMemorySize, GEMM_SMEM);
    cudaFuncSetAttribute(gemm_out_kernel,
                         cudaFuncAttributeMaxDynamicSharedMemorySize, GEMM_OUT_SMEM);
    cudaFuncSetAttribute(attention_kernel,
                         cudaFuncAttributeMaxDynamicSharedMemorySize, ATT_SMEM);

    // merged fp16 pre-conversion
    cvt_all_kernel<<<(CVT_TOTAL + 255) / 256, 256>>>(
        query, context, Wq, Wk, Wv, Wp, hq, hc, w0, w1, w2, w3);

    // merged Q/K/V projections (+ fused LN for Q,K)
    qkv_kernel<<<1152, 256, GEMM_SMEM>>>(hq, hc, w0, w1, w2, hQ, hK, hV,
                                         qg, qb, kg, kb);

    // Fused attention
    {
        dim3 ga(Nq / 32, Bz * Hh);
        attention_kernel<<<ga, 256, ATT_SMEM>>>(hQ, hK, hV, mask, attn, hO);
    }

    // Output projection + bias (128x64 tiles, 256 CTAs)
    {
        dim3 go(Cd / 64, (Bz * Nq) / 128);   // 16 x 16
        gemm_out_kernel<<<go, 256, GEMM_OUT_SMEM>>>(hO, w3, bp, out, Cd, Cd);
    }
}

// round 15
// speedup vs baseline: 1.0296x; 1.0296x over previous
#include <cuda_runtime.h>
#include <cuda_fp16.h>
#include <math.h>
#include <stdint.h>

// Problem constants
constexpr int Bz = 8;
constexpr int Nq = 256;
constexpr int Mc = 1024;
constexpr int Cd = 1024;
constexpr int Hh = 16;

// Scratch
__device__ __half g_hQ[Bz * Nq * Cd];
__device__ __half g_hK[Bz * Mc * Cd];
__device__ __half g_hV[Bz * Mc * Cd];
__device__ __half g_hO[Bz * Nq * Cd];
__device__ __half g_hq[Bz * Nq * Cd];
__device__ __half g_hc[Bz * Mc * Cd];
__device__ __half g_w0[Cd * Cd];
__device__ __half g_w1[Cd * Cd];
__device__ __half g_w2[Cd * Cd];
__device__ __half g_w3[Cd * Cd];

// ---------------------------------------------------------------------------
// PTX helpers
// ---------------------------------------------------------------------------
__device__ __forceinline__ void cp_async16(uint32_t saddr, const void* gptr) {
    asm volatile("cp.async.ca.shared.global [%0], [%1], 16;" ::
                 "r"(saddr), "l"(gptr));
}
__device__ __forceinline__ void cp_commit() { asm volatile("cp.async.commit_group;"); }
__device__ __forceinline__ void cp_wait0()  { asm volatile("cp.async.wait_group 0;"); }
__device__ __forceinline__ void cp_wait1()  { asm volatile("cp.async.wait_group 1;"); }

__device__ __forceinline__ void mma_f16_16816(float c[4], uint32_t a0, uint32_t a1,
                                              uint32_t a2, uint32_t a3,
                                              uint32_t b0, uint32_t b1) {
    asm volatile(
        "mma.sync.aligned.m16n8k16.row.col.f32.f16.f16.f32 "
        "{%0,%1,%2,%3}, {%4,%5,%6,%7}, {%8,%9}, {%0,%1,%2,%3};"
        : "+f"(c[0]), "+f"(c[1]), "+f"(c[2]), "+f"(c[3])
        : "r"(a0), "r"(a1), "r"(a2), "r"(a3), "r"(b0), "r"(b1));
}
__device__ __forceinline__ void ldsm_x4(uint32_t& r0, uint32_t& r1, uint32_t& r2,
                                        uint32_t& r3, uint32_t addr) {
    asm volatile("ldmatrix.sync.aligned.m8n8.x4.shared.b16 {%0,%1,%2,%3}, [%4];"
                 : "=r"(r0), "=r"(r1), "=r"(r2), "=r"(r3) : "r"(addr));
}
__device__ __forceinline__ void ldsm_x2(uint32_t& r0, uint32_t& r1, uint32_t addr) {
    asm volatile("ldmatrix.sync.aligned.m8n8.x2.shared.b16 {%0,%1}, [%2];"
                 : "=r"(r0), "=r"(r1) : "r"(addr));
}
__device__ __forceinline__ void ldsm_x2t(uint32_t& r0, uint32_t& r1, uint32_t addr) {
    asm volatile("ldmatrix.sync.aligned.m8n8.x2.trans.shared.b16 {%0,%1}, [%2];"
                 : "=r"(r0), "=r"(r1) : "r"(addr));
}
__device__ __forceinline__ uint32_t h2u(__half2 h) {
    return *reinterpret_cast<uint32_t*>(&h);
}

// ---------------------------------------------------------------------------
// Merged fp32->fp16 conversion (one launch)
// ---------------------------------------------------------------------------
constexpr int CVT_NQ = Bz * Nq * Cd / 4;
constexpr int CVT_NC = Bz * Mc * Cd / 4;
constexpr int CVT_NW = Cd * Cd / 4;
constexpr int CVT_TOTAL = CVT_NQ + CVT_NC + 4 * CVT_NW;

__global__ void cvt_all_kernel(const float* __restrict__ q, const float* __restrict__ c,
                               const float* __restrict__ wq, const float* __restrict__ wk,
                               const float* __restrict__ wv, const float* __restrict__ wp,
                               __half* hq, __half* hc, __half* h0, __half* h1,
                               __half* h2, __half* h3) {
    int i = blockIdx.x * blockDim.x + threadIdx.x;
    if (i >= CVT_TOTAL) return;
    const float* in; __half* out; int off;
    if (i < CVT_NQ)                    { in = q;  out = hq; off = i; }
    else if (i < CVT_NQ + CVT_NC)      { in = c;  out = hc; off = i - CVT_NQ; }
    else {
        int j = i - CVT_NQ - CVT_NC;
        int seg = j / CVT_NW;
        off = j - seg * CVT_NW;
        in  = (seg == 0) ? wq : (seg == 1) ? wk : (seg == 2) ? wv : wp;
        out = (seg == 0) ? h0 : (seg == 1) ? h1 : (seg == 2) ? h2 : h3;
    }
    float4 v = ((const float4*)in)[off];
    ((__half2*)out)[2 * off]     = __floats2half2_rn(v.x, v.y);
    ((__half2*)out)[2 * off + 1] = __floats2half2_rn(v.z, v.w);
}

// ---------------------------------------------------------------------------
// Shared GEMM body (R10/R13-proven): 128x128 CTA, 8 warps, kTile=64.
// ---------------------------------------------------------------------------
constexpr int GEMM_SMEM = 2 * 2 * 128 * 72 * 2;  // 73728

__device__ __forceinline__
void gemm_body_f16(const __half* __restrict__ A, const __half* __restrict__ Bw,
                   __half* __restrict__ Ch, const float* __restrict__ gamma,
                   const float* __restrict__ beta, int brow, int bcol,
                   int Nb, int K, __half* smh) {
    __half* As = smh;
    __half* Bs = smh + 2 * 128 * 72;

    const int tid  = threadIdx.x;
    const int lane = tid & 31;
    const int w    = tid >> 5;
    const int wm   = (w & 1) * 64;
    const int wn   = (w >> 1) * 32;
    const int g    = lane >> 2;
    const int ti   = lane & 3;
    const int lt   = lane >> 3;
    const int lr8  = lane & 7;

    const int lrow = tid >> 1;
    const int lh   = (tid & 1) * 32;
    const __half* Ag = A  + (size_t)(brow + lrow) * K + lh;
    const __half* Bg = Bw + (size_t)(bcol + lrow) * K + lh;
    const uint32_t sa = (uint32_t)__cvta_generic_to_shared(&As[lrow * 72 + lh]);
    const uint32_t sb = (uint32_t)__cvta_generic_to_shared(&Bs[lrow * 72 + lh]);
    const uint32_t asBase = (uint32_t)__cvta_generic_to_shared(As);
    const uint32_t bsBase = (uint32_t)__cvta_generic_to_shared(Bs);
    const uint32_t stageB = 128 * 72 * 2;

    uint32_t aoff[4], boff[2];
#pragma unroll
    for (int mt = 0; mt < 4; mt++) {
        int row = wm + mt * 16 + ((lt & 1) << 3) + lr8;
        int col = (lt >> 1) << 3;
        aoff[mt] = (uint32_t)((row * 72 + col) * 2);
    }
#pragma unroll
    for (int p = 0; p < 2; p++) {
        int row = wn + p * 16 + ((lt >> 1) << 3) + lr8;
        int col = (lt & 1) << 3;
        boff[p] = (uint32_t)((row * 72 + col) * 2);
    }

    float c[4][4][4];
#pragma unroll
    for (int mt = 0; mt < 4; mt++)
#pragma unroll
        for (int nt = 0; nt < 4; nt++)
#pragma unroll
            for (int e = 0; e < 4; e++) c[mt][nt][e] = 0.f;

    const int niter = K / 64;

#pragma unroll
    for (int v = 0; v < 4; v++) {
        cp_async16(sa + v * 16, Ag + v * 8);
        cp_async16(sb + v * 16, Bg + v * 8);
    }
    cp_commit();
    cp_wait0();
    __syncthreads();

    for (int t = 0; t < niter; t++) {
        if (t + 1 < niter) {
            const int k0 = (t + 1) * 64;
            const uint32_t so = ((t + 1) & 1) * stageB;
#pragma unroll
            for (int v = 0; v < 4; v++) {
                cp_async16(sa + so + v * 16, Ag + k0 + v * 8);
                cp_async16(sb + so + v * 16, Bg + k0 + v * 8);
            }
            cp_commit();
        }

        const uint32_t so = (t & 1) * stageB;

#pragma unroll
        for (int ks = 0; ks < 4; ks++) {
            const uint32_t kk2 = ks * 32;
            uint32_t a[4][4], b[4][2];
#pragma unroll
            for (int mt = 0; mt < 4; mt++)
                ldsm_x4(a[mt][0], a[mt][1], a[mt][2], a[mt][3],
                        asBase + so + aoff[mt] + kk2);
#pragma unroll
            for (int p = 0; p < 2; p++)
                ldsm_x4(b[2 * p][0], b[2 * p][1], b[2 * p + 1][0], b[2 * p + 1][1],
                        bsBase + so + boff[p] + kk2);
#pragma unroll
            for (int mt = 0; mt < 4; mt++)
#pragma unroll
                for (int nt = 0; nt < 4; nt++)
                    mma_f16_16816(c[mt][nt], a[mt][0], a[mt][1], a[mt][2],
                                  a[mt][3], b[nt][0], b[nt][1]);
        }

        if (t + 1 < niter) {
            cp_wait0();
            __syncthreads();
        }
    }

    if (gamma != nullptr) {
        __syncthreads();
        float* St = (float*)smh;   // [128][132]
#pragma unroll
        for (int mt = 0; mt < 4; mt++)
#pragma unroll
            for (int nt = 0; nt < 4; nt++) {
                const int r0 = wm + mt * 16 + g;
                const int c0 = wn + nt * 8 + 2 * ti;
                *(float2*)&St[r0 * 132 + c0] =
                    make_float2(c[mt][nt][0], c[mt][nt][1]);
                *(float2*)&St[(r0 + 8) * 132 + c0] =
                    make_float2(c[mt][nt][2], c[mt][nt][3]);
            }
        __syncthreads();

        const int row = tid & 127;
        const int grp = tid >> 7;
        const float* pr = St + row * 132 + grp * 64;
        float s = 0.f, sq = 0.f;
#pragma unroll
        for (int i2 = 0; i2 < 16; i2++) {
            float4 v = *(const float4*)(pr + i2 * 4);
            s  += v.x + v.y + v.z + v.w;
            sq += v.x * v.x + v.y * v.y + v.z * v.z + v.w * v.w;
        }
        const float mean = s * (1.f / 64.f);
        const float var  = sq * (1.f / 64.f) - mean * mean;
        const float rstd = rsqrtf(var + 1e-5f);

        __half* yp = Ch + (size_t)(brow + row) * Nb + bcol + grp * 64;
#pragma unroll
        for (int i2 = 0; i2 < 16; i2++) {
            float4 v  = *(const float4*)(pr + i2 * 4);
            float4 gv = *(const float4*)(gamma + i2 * 4);
            float4 bv = *(const float4*)(beta + i2 * 4);
            *(__half2*)(yp + i2 * 4) =
                __floats2half2_rn((v.x - mean) * rstd * gv.x + bv.x,
                                  (v.y - mean) * rstd * gv.y + bv.y);
            *(__half2*)(yp + i2 * 4 + 2) =
                __floats2half2_rn((v.z - mean) * rstd * gv.z + bv.z,
                                  (v.w - mean) * rstd * gv.w + bv.w);
        }
        return;
    }

#pragma unroll
    for (int mt = 0; mt < 4; mt++) {
#pragma unroll
        for (int nt = 0; nt < 4; nt++) {
            const int row0 = brow + wm + mt * 16 + g;
            const int col0 = bcol + wn + nt * 8 + 2 * ti;
            *(__half2*)(Ch + (size_t)row0 * Nb + col0) =
                __floats2half2_rn(c[mt][nt][0], c[mt][nt][1]);
            *(__half2*)(Ch + (size_t)(row0 + 8) * Nb + col0) =
                __floats2half2_rn(c[mt][nt][2], c[mt][nt][3]);
        }
    }
}

// Merged Q/K/V projection launch: 1152 CTAs, flattened dispatch.
__global__ __launch_bounds__(256, 2)
void qkv_kernel(const __half* __restrict__ hq, const __half* __restrict__ hc,
                const __half* __restrict__ w0, const __half* __restrict__ w1,
                const __half* __restrict__ w2,
                __half* __restrict__ hQ, __half* __restrict__ hK,
                __half* __restrict__ hV,
                const float* __restrict__ qg, const float* __restrict__ qb,
                const float* __restrict__ kg, const float* __restrict__ kb) {
    extern __shared__ __half smh[];
    const int bxx = blockIdx.x;
    const __half *A, *Bw;
    __half* Ch;
    const float *gamma, *beta;
    int gx, gy;
    if (bxx < 128) {
        gx = bxx & 7; gy = bxx >> 3;
        A = hq; Bw = w0; Ch = hQ; gamma = qg; beta = qb;
    } else if (bxx < 640) {
        int idx = bxx - 128;
        gx = idx & 7; gy = idx >> 3;
        A = hc; Bw = w1; Ch = hK; gamma = kg; beta = kb;
    } else {
        int idx = bxx - 640;
        gx = idx & 7; gy = idx >> 3;
        A = hc; Bw = w2; Ch = hV; gamma = nullptr; beta = nullptr;
    }
    gemm_body_f16(A, Bw, Ch, gamma, beta, gy * 128, gx * 128, Cd, Cd, smh);
}

// Output projection (R13-proven): 128x128 CTA, fp32 out + bias.
__global__ __launch_bounds__(256, 2)
void gemm_out_kernel(const __half* __restrict__ A, const __half* __restrict__ Bw,
                     const float* __restrict__ bias, float* __restrict__ Cc,
                     int Nb, int K) {
    extern __shared__ __half smh[];
    __half* As = smh;
    __half* Bs = smh + 2 * 128 * 72;

    const int tid  = threadIdx.x;
    const int lane = tid & 31;
    const int w    = tid >> 5;
    const int wm   = (w & 1) * 64;
    const int wn   = (w >> 1) * 32;
    const int g    = lane >> 2;
    const int ti   = lane & 3;
    const int lt   = lane >> 3;
    const int lr8  = lane & 7;
    const int brow = blockIdx.y * 128;
    const int bcol = blockIdx.x * 128;

    const int lrow = tid >> 1;
    const int lh   = (tid & 1) * 32;
    const __half* Ag = A  + (size_t)(brow + lrow) * K + lh;
    const __half* Bg = Bw + (size_t)(bcol + lrow) * K + lh;
    const uint32_t sa = (uint32_t)__cvta_generic_to_shared(&As[lrow * 72 + lh]);
    const uint32_t sb = (uint32_t)__cvta_generic_to_shared(&Bs[lrow * 72 + lh]);
    const uint32_t asBase = (uint32_t)__cvta_generic_to_shared(As);
    const uint32_t bsBase = (uint32_t)__cvta_generic_to_shared(Bs);
    const uint32_t stageB = 128 * 72 * 2;

    uint32_t aoff[4], boff[2];
#pragma unroll
    for (int mt = 0; mt < 4; mt++) {
        int row = wm + mt * 16 + ((lt & 1) << 3) + lr8;
        int col = (lt >> 1) << 3;
        aoff[mt] = (uint32_t)((row * 72 + col) * 2);
    }
#pragma unroll
    for (int p = 0; p < 2; p++) {
        int row = wn + p * 16 + ((lt >> 1) << 3) + lr8;
        int col = (lt & 1) << 3;
        boff[p] = (uint32_t)((row * 72 + col) * 2);
    }

    float c[4][4][4];
#pragma unroll
    for (int mt = 0; mt < 4; mt++)
#pragma unroll
        for (int nt = 0; nt < 4; nt++)
#pragma unroll
            for (int e = 0; e < 4; e++) c[mt][nt][e] = 0.f;

    const int niter = K / 64;

#pragma unroll
    for (int v = 0; v < 4; v++) {
        cp_async16(sa + v * 16, Ag + v * 8);
        cp_async16(sb + v * 16, Bg + v * 8);
    }
    cp_commit();
    cp_wait0();
    __syncthreads();

    for (int t = 0; t < niter; t++) {
        if (t + 1 < niter) {
            const int k0 = (t + 1) * 64;
            const uint32_t so = ((t + 1) & 1) * stageB;
#pragma unroll
            for (int v = 0; v < 4; v++) {
                cp_async16(sa + so + v * 16, Ag + k0 + v * 8);
                cp_async16(sb + so + v * 16, Bg + k0 + v * 8);
            }
            cp_commit();
        }

        const uint32_t so = (t & 1) * stageB;

#pragma unroll
        for (int ks = 0; ks < 4; ks++) {
            const uint32_t kk2 = ks * 32;
            uint32_t a[4][4], b[4][2];
#pragma unroll
            for (int mt = 0; mt < 4; mt++)
                ldsm_x4(a[mt][0], a[mt][1], a[mt][2], a[mt][3],
                        asBase + so + aoff[mt] + kk2);
#pragma unroll
            for (int p = 0; p < 2; p++)
                ldsm_x4(b[2 * p][0], b[2 * p][1], b[2 * p + 1][0], b[2 * p + 1][1],
                        bsBase + so + boff[p] + kk2);
#pragma unroll
            for (int mt = 0; mt < 4; mt++)
#pragma unroll
                for (int nt = 0; nt < 4; nt++)
                    mma_f16_16816(c[mt][nt], a[mt][0], a[mt][1], a[mt][2],
                                  a[mt][3], b[nt][0], b[nt][1]);
        }

        if (t + 1 < niter) {
            cp_wait0();
            __syncthreads();
        }
    }

#pragma unroll
    for (int mt = 0; mt < 4; mt++) {
#pragma unroll
        for (int nt = 0; nt < 4; nt++) {
            const int row0 = brow + wm + mt * 16 + g;
            const int col0 = bcol + wn + nt * 8 + 2 * ti;
            const float b0 = bias[col0], b1 = bias[col0 + 1];
            *(float2*)(Cc + (size_t)row0 * Nb + col0) =
                make_float2(c[mt][nt][0] + b0, c[mt][nt][1] + b1);
            *(float2*)(Cc + (size_t)(row0 + 8) * Nb + col0) =
                make_float2(c[mt][nt][2] + b0, c[mt][nt][3] + b1);
        }
    }
}

// ---------------------------------------------------------------------------
// Fused attention: 16 q-rows per CTA -> 95.7KB smem -> 2 CTAs/SM.
// 3-buffer cp.async pipeline, 1 sync per chunk (R13 pipeline).
// ---------------------------------------------------------------------------
constexpr int SPITCH   = 1028;
constexpr int ATT_SMEM = 16 * SPITCH * 4 + 16 * 72 * 2 + 3 * 64 * 72 * 2;  // 95744

__global__ __launch_bounds__(256)
void attention_kernel(const __half* __restrict__ Qh16, const __half* __restrict__ Kh16,
                      const __half* __restrict__ Vh16, const int* __restrict__ mask,
                      float* __restrict__ attn, __half* __restrict__ O) {
    extern __shared__ char smraw[];
    float*  S  = (float*)smraw;                                    // [16][SPITCH]
    __half* Qh = (__half*)(smraw + 16 * SPITCH * 4);               // [16][72]
    __half* KV = (__half*)(smraw + 16 * SPITCH * 4 + 16 * 72 * 2); // [3][64][72]

    const int bh = blockIdx.y;
    const int b  = bh >> 4;
    const int h  = bh & 15;
    const int n0 = blockIdx.x * 16;
    const int tid  = threadIdx.x;
    const int lane = tid & 31;
    const int w    = tid >> 5;
    const int g    = lane >> 2;
    const int ti   = lane & 3;
    const int lt   = lane >> 3;
    const int lr8  = lane & 7;
    const int l16  = lane & 15;

    const uint32_t sBase  = (uint32_t)__cvta_generic_to_shared(smraw);
    const uint32_t qBase  = (uint32_t)__cvta_generic_to_shared(Qh);
    const uint32_t kvBase = (uint32_t)__cvta_generic_to_shared(KV);
    const uint32_t bufB   = 64 * 72 * 2;  // 9216

    // ---- load Q tile [16 n][64 d] fp16 (first 128 threads) ----
    if (tid < 128) {
        const int n  = tid >> 3;
        const int d0 = (tid & 7) * 8;
        const __half* qp = Qh16 + (size_t)(b * Nq + n0 + n) * Cd + h * 64 + d0;
        *(uint4*)&Qh[n * 72 + d0] = *(const uint4*)qp;
    }
    __syncthreads();

    // Q fragments: single 16-row m-tile, hoisted over all chunks
    uint32_t qa[4][4];
    {
        const uint32_t off = qBase +
            (uint32_t)(((((lt & 1) << 3) + lr8) * 72 + ((lt >> 1) << 3)) * 2);
#pragma unroll
        for (int ks = 0; ks < 4; ks++)
            ldsm_x4(qa[ks][0], qa[ks][1], qa[ks][2], qa[ks][3], off + ks * 32);
    }

    const int stM  = tid >> 2;
    const int stD0 = (tid & 3) * 16;
    const uint32_t stOff = (uint32_t)((stM * 72 + stD0) * 2);
    const __half* Kbase = Kh16 + (size_t)(b * Mc + stM) * Cd + h * 64 + stD0;
    const __half* Vbase = Vh16 + (size_t)(b * Mc + stM) * Cd + h * 64 + stD0;

    const float scale = 0.125f;
    const uint32_t kboff = (uint32_t)(((w * 8 + (l16 & 7)) * 72 + ((l16 >> 3) << 3)) * 2);

    // ---- pass 1: scores ----
#pragma unroll
    for (int p = 0; p < 2; p++) {
        const uint32_t dst = kvBase + p * bufB + stOff;
        const __half* kp = Kbase + (size_t)p * 64 * Cd;
        cp_async16(dst, kp);
        cp_async16(dst + 16, kp + 8);
        cp_commit();
    }

    for (int j = 0; j < 16; j++) {
        if (j < 15) cp_wait1(); else cp_wait0();
        __syncthreads();
        if (j + 2 < 16) {
            const uint32_t dst = kvBase + ((j + 2) % 3) * bufB + stOff;
            const __half* kp = Kbase + (size_t)(j + 2) * 64 * Cd;
            cp_async16(dst, kp);
            cp_async16(dst + 16, kp + 8);
            cp_commit();
        }

        float c[4] = {0.f, 0.f, 0.f, 0.f};
        const uint32_t kb = kvBase + (j % 3) * bufB + kboff;
#pragma unroll
        for (int ks = 0; ks < 4; ks++) {
            uint32_t b0, b1;
            ldsm_x2(b0, b1, kb + ks * 32);
            mma_f16_16816(c, qa[ks][0], qa[ks][1], qa[ks][2], qa[ks][3], b0, b1);
        }

        const int m0 = j * 64 + w * 8 + 2 * ti;
        const bool ok0 = mask[b * Mc + m0] != 0;
        const bool ok1 = mask[b * Mc + m0 + 1] != 0;
        S[g * SPITCH + m0]           = ok0 ? c[0] * scale : -1e30f;
        S[g * SPITCH + m0 + 1]       = ok1 ? c[1] * scale : -1e30f;
        S[(g + 8) * SPITCH + m0]     = ok0 ? c[2] * scale : -1e30f;
        S[(g + 8) * SPITCH + m0 + 1] = ok1 ? c[3] * scale : -1e30f;
    }
    __syncthreads();

    // prefetch V chunks 0,1 — overlaps with softmax
#pragma unroll
    for (int p = 0; p < 2; p++) {
        const uint32_t dst = kvBase + p * bufB + stOff;
        const __half* vp = Vbase + (size_t)p * 64 * Cd;
        cp_async16(dst, vp);
        cp_async16(dst + 16, vp + 8);
        cp_commit();
    }

    // ---- pass 2: softmax (2 rows per warp); write attn fp32 + fp16 in-place
    for (int r = 0; r < 2; r++) {
        const int n = w * 2 + r;
        float* p = S + (size_t)n * SPITCH;

        float4 v[8];
        float mx = -1e30f;
#pragma unroll
        for (int i = 0; i < 8; i++) {
            v[i] = *(const float4*)(p + (i * 32 + lane) * 4);
            mx = fmaxf(mx, fmaxf(fmaxf(v[i].x, v[i].y), fmaxf(v[i].z, v[i].w)));
        }
#pragma unroll
        for (int o = 16; o > 0; o >>= 1) mx = fmaxf(mx, __shfl_xor_sync(0xFFFFFFFFu, mx, o));

        float sum = 0.f;
#pragma unroll
        for (int i = 0; i < 8; i++) {
            v[i].x = __expf(v[i].x - mx);
            v[i].y = __expf(v[i].y - mx);
            v[i].z = __expf(v[i].z - mx);
            v[i].w = __expf(v[i].w - mx);
            sum += v[i].x + v[i].y + v[i].z + v[i].w;
        }
#pragma unroll
        for (int o = 16; o > 0; o >>= 1) sum += __shfl_xor_sync(0xFFFFFFFFu, sum, o);
        const float inv = 1.f / sum;

        float*  op = attn + ((size_t)bh * Nq + n0 + n) * Mc;
        __half* ph = (__half*)p;
#pragma unroll
        for (int i = 0; i < 8; i++) {
            const int m0 = (i * 32 + lane) * 4;
            v[i].x *= inv; v[i].y *= inv; v[i].z *= inv; v[i].w *= inv;
            *(float4*)(op + m0) = v[i];
            uint2 hp;
            hp.x = h2u(__floats2half2_rn(v[i].x, v[i].y));
            hp.y = h2u(__floats2half2_rn(v[i].z, v[i].w));
            *(uint2*)(ph + m0) = hp;
        }
    }

    // ---- pass 3: AV ----
    uint32_t sfoff;
    {
        const int row = ((lt & 1) << 3) + lr8;
        sfoff = (uint32_t)(row * (SPITCH * 4) + (((lt >> 1) << 3)) * 2);
    }
    const uint32_t vboff = (uint32_t)((l16 * 72 + w * 8) * 2);

    float o2[4] = {0.f, 0.f, 0.f, 0.f};

    for (int j = 0; j < 16; j++) {
        if (j < 15) cp_wait1(); else cp_wait0();
        __syncthreads();
        if (j + 2 < 16) {
            const uint32_t dst = kvBase + ((j + 2) % 3) * bufB + stOff;
            const __half* vp = Vbase + (size_t)(j + 2) * 64 * Cd;
            cp_async16(dst, vp);
            cp_async16(dst + 16, vp + 8);
            cp_commit();
        }

        const uint32_t vb = kvBase + (j % 3) * bufB + vboff;
#pragma unroll
        for (int ks = 0; ks < 4; ks++) {
            uint32_t a[4], b0, b1;
            const uint32_t colB = (uint32_t)((j * 64 + ks * 16) * 2);
            ldsm_x4(a[0], a[1], a[2], a[3], sBase + sfoff + colB);
            ldsm_x2t(b0, b1, vb + ks * 2304);
            mma_f16_16816(o2, a[0], a[1], a[2], a[3], b0, b1);
        }
    }

    // write O fp16: rows n0+g, n0+g+8; cols h*64 + w*8 + 2ti
    {
        const int col = h * 64 + w * 8 + 2 * ti;
        *(__half2*)(O + (size_t)(b * Nq + n0 + g) * Cd + col) =
            __floats2half2_rn(o2[0], o2[1]);
        *(__half2*)(O + (size_t)(b * Nq + n0 + g + 8) * Cd + col) =
            __floats2half2_rn(o2[2], o2[3]);
    }
}

// ---------------------------------------------------------------------------
// Launch
// ---------------------------------------------------------------------------
extern "C" void kernel_launch(void* const* d_in, const int* in_sizes, int n_in,
                              void* d_out, int out_size) {
    const float* query   = (const float*)d_in[0];
    const float* context = (const float*)d_in[1];
    const int*   mask    = (const int*)d_in[2];
    const float* Wq      = (const float*)d_in[3];
    const float* Wk      = (const float*)d_in[4];
    const float* Wv      = (const float*)d_in[5];
    const float* qg      = (const float*)d_in[6];
    const float* qb      = (const float*)d_in[7];
    const float* kg      = (const float*)d_in[8];
    const float* kb      = (const float*)d_in[9];
    const float* Wp      = (const float*)d_in[10];
    const float* bp      = (const float*)d_in[11];

    float* out  = (float*)d_out;
    float* attn = out + (size_t)Bz * Nq * Cd;

    __half *hQ, *hK, *hV, *hO, *hq, *hc, *w0, *w1, *w2, *w3;
    cudaGetSymbolAddress((void**)&hQ, g_hQ);
    cudaGetSymbolAddress((void**)&hK, g_hK);
    cudaGetSymbolAddress((void**)&hV, g_hV);
    cudaGetSymbolAddress((void**)&hO, g_hO);
    cudaGetSymbolAddress((void**)&hq, g_hq);
    cudaGetSymbolAddress((void**)&hc, g_hc);
    cudaGetSymbolAddress((void**)&w0, g_w0);
    cudaGetSymbolAddress((void**)&w1, g_w1);
    cudaGetSymbolAddress((void**)&w2, g_w2);
    cudaGetSymbolAddress((void**)&w3, g_w3);

    cudaFuncSetAttribute(qkv_kernel,
                         cudaFuncAttributeMaxDynamicSharedMemorySize, GEMM_SMEM);
    cudaFuncSetAttribute(gemm_out_kernel,
                         cudaFuncAttributeMaxDynamicSharedMemorySize, GEMM_SMEM);
    cudaFuncSetAttribute(attention_kernel,
                         cudaFuncAttributeMaxDynamicSharedMemorySize, ATT_SMEM);

    // merged fp16 pre-conversion
    cvt_all_kernel<<<(CVT_TOTAL + 255) / 256, 256>>>(
        query, context, Wq, Wk, Wv, Wp, hq, hc, w0, w1, w2, w3);

    // merged Q/K/V projections (+ fused LN for Q,K)
    qkv_kernel<<<1152, 256, GEMM_SMEM>>>(hq, hc, w0, w1, w2, hQ, hK, hV,
                                         qg, qb, kg, kb);

    // Fused attention (16 q-rows/CTA, 2 CTAs/SM)
    {
        dim3 ga(Nq / 16, Bz * Hh);   // 16 x 128 = 2048 CTAs
        attention_kernel<<<ga, 256, ATT_SMEM>>>(hQ, hK, hV, mask, attn, hO);
    }

    // Output projection + bias (R13 config)
    {
        dim3 go(Cd / 128, (Bz * Nq) / 128);   // 8 x 16
        gemm_out_kernel<<<go, 256, GEMM_SMEM>>>(hO, w3, bp, out, Cd, Cd);
    }
}